// round 15
// baseline (speedup 1.0000x reference)
#include <cuda_runtime.h>

// SoftCLDiceLoss on [8,2,1024,1024]:
//   p = sigmoid(pred), t = target
//   skel(x) = 1 - prod_{k=0..10} (1 - relu(E_k - dilate(E_{k+1}))),  E_k = erode^k(clip(x))
//   erode = 3x3 min (pad +inf), dilate = 3x3 max (pad -inf)
//   tprec = sum(skel_p*t)/(sum(skel_p)+eps); tsens = sum(skel_t*p)/(sum(skel_t)+eps)
//   loss = mean(1 - 2*tprec*tsens/(tprec+tsens+eps))
//
// 3 sweeps total: quad (steps k..k+3, halo 5) x2, then 3-step final
// (steps 8..10, halo 4) fused with the reduction. 1 col/lane register sweep,
// depth-4 prefetch pipelines. Masked-only sweeps (no interior specialization)
// to keep compiled code small.

#define IMG_W    1024
#define IMG_H    1024
#define NPLANES  16
#define PLANE_SZ (IMG_W * IMG_H)

#define STRIP   128
#define COLS4   22             // 32 - 2*5 halo (quad kernel)
#define TILES4  47             // ceil(1024/22)
#define COLSF   24             // 32 - 2*4 halo (final kernel)
#define TILESF  43             // ceil(1024/24)

__device__ float g_E[2][2][NPLANES * PLANE_SZ];   // [skel][pingpong]
__device__ float g_acc[2][NPLANES * PLANE_SZ];
__device__ float g_sums[NPLANES * 4];

__device__ __forceinline__ float min3f(float a, float b, float c) { return fminf(a, fminf(b, c)); }
__device__ __forceinline__ float max3f(float a, float b, float c) { return fmaxf(a, fmaxf(b, c)); }
__device__ __forceinline__ float sigmoidf(float x) { return 1.0f / (1.0f + __expf(-x)); }

__device__ __forceinline__ float hmin3(float v) {
    float l = __shfl_up_sync(0xffffffffu, v, 1);
    float r = __shfl_down_sync(0xffffffffu, v, 1);
    return min3f(l, v, r);
}
__device__ __forceinline__ float hmax3(float v) {
    float l = __shfl_up_sync(0xffffffffu, v, 1);
    float r = __shfl_down_sync(0xffffffffu, v, 1);
    return max3f(l, v, r);
}

__global__ void zero_sums_kernel() {
    int i = threadIdx.x;
    if (i < NPLANES * 4) g_sums[i] = 0.0f;
}

// ---------------------------------------------------------------------------
// Quad kernel: steps k..k+3. Reads E_k, writes E_{k+4},
// acc *= prod_{s=k..k+3}(1-delta_s). Output row = r-5; output lanes 5..26.
// ---------------------------------------------------------------------------
template<bool FIRST>
__global__ __launch_bounds__(128) void quad_kernel(
    const float* __restrict__ pred,
    const float* __restrict__ target,
    int srcbuf, int dstbuf)
{
    const int z     = blockIdx.z;
    const int skel  = z >> 4;
    const int plane = z & 15;
    const int wtile = blockIdx.x * 4 + (threadIdx.x >> 5);
    if (wtile >= TILES4) return;
    const int  lane = threadIdx.x & 31;
    const int  gx   = wtile * COLS4 - 5 + lane;
    const int  y0   = blockIdx.y * STRIP;
    const int  yEnd = y0 + STRIP;
    const bool inX  = (unsigned)gx < (unsigned)IMG_W;
    const bool outL = (lane >= 5) & (lane <= 26) & inX;

    const size_t pbase = (size_t)plane * PLANE_SZ;
    const float* __restrict__ src = FIRST ? ((skel ? target : pred) + pbase)
                                          : (const float*)&g_E[skel][srcbuf][pbase];
    float* __restrict__ dst = &g_E[skel][dstbuf][pbase];
    float* __restrict__ acc = &g_acc[skel][pbase];

    auto ldrow = [&](int rr) -> float {
        float v = 1e30f;
        if (((unsigned)rr < (unsigned)IMG_H) & inX) {
            float x = __ldg(&src[(size_t)rr * IMG_W + gx]);
            v = FIRST ? (skel ? __saturatef(x) : sigmoidf(x)) : x;
        }
        return v;
    };

    float abuf[4];
    float accbuf[4] = {0.f, 0.f, 0.f, 0.f};
    #pragma unroll
    for (int j = 0; j < 4; j++) abuf[j] = ldrow(y0 - 7 + j);

    float h1m1=0,h1m2=0,h1dm1=0,h1dm2=0;
    float h2m1=0,h2m2=0,h2dm1=0,h2dm2=0;
    float h3m1=0,h3m2=0,h3dm1=0,h3dm2=0;
    float h4m1=0,h4m2=0,h4dm1=0,h4dm2=0;
    float ad1=0,ad2=0,e1d1=0,e1d2=0,e2d1=0,e2d2=0,e3d1=0,e3d2=0;
    float mk0d1=0,mk0d2=0,mk0d3=0,mk1d1=0,mk1d2=0,mk2d1=0;

    // rows y0-7 .. yEnd+4 (STRIP+12 iters, multiple of 4); slot j == (r-(y0-7)) mod 4
    for (int rb = y0 - 7; rb <= yEnd + 1; rb += 4) {
        #pragma unroll
        for (int j = 0; j < 4; j++) {
            const int r = rb + j;
            float a = abuf[j];
            abuf[j] = ldrow(r + 4);                     // consumed 4 iters later
            float av = 0.f;
            if (!FIRST) {
                av = accbuf[j];                         // acc row r-5
                if (((r - 1) >= y0) & ((r - 1) < yEnd) & outL)
                    accbuf[j] = acc[(size_t)(r - 1) * IMG_W + gx];  // consumed 4 iters later
            }

            float h1 = hmin3(a);                                // row r
            float e1 = min3f(h1m2, h1m1, h1);                   // E_{k+1}, r-1
            bool  m1 = ((unsigned)(r - 1) < (unsigned)IMG_H) & inX;
            float h1d = hmax3(m1 ? e1 : -1e30f);
            float h2  = hmin3(m1 ? e1 :  1e30f);
            float e2 = min3f(h2m2, h2m1, h2);                   // E_{k+2}, r-2
            bool  m2 = ((unsigned)(r - 2) < (unsigned)IMG_H) & inX;
            float h2d = hmax3(m2 ? e2 : -1e30f);
            float h3  = hmin3(m2 ? e2 :  1e30f);
            float e3 = min3f(h3m2, h3m1, h3);                   // E_{k+3}, r-3
            bool  m3 = ((unsigned)(r - 3) < (unsigned)IMG_H) & inX;
            float h3d = hmax3(m3 ? e3 : -1e30f);
            float h4  = hmin3(m3 ? e3 :  1e30f);
            float e4 = min3f(h4m2, h4m1, h4);                   // E_{k+4}, r-4
            bool  m4 = ((unsigned)(r - 4) < (unsigned)IMG_H) & inX;
            float h4d = hmax3(m4 ? e4 : -1e30f);

            float d1  = max3f(h1dm2, h1dm1, h1d);               // dilate(E_{k+1}), r-2
            float mk0 = 1.f - fmaxf(ad2 - d1, 0.f);             // 1-delta_k, r-2
            float d2  = max3f(h2dm2, h2dm1, h2d);               // dilate(E_{k+2}), r-3
            float mk1 = 1.f - fmaxf(e1d2 - d2, 0.f);            // 1-delta_{k+1}, r-3
            float d3  = max3f(h3dm2, h3dm1, h3d);               // dilate(E_{k+3}), r-4
            float mk2 = 1.f - fmaxf(e2d2 - d3, 0.f);            // 1-delta_{k+2}, r-4
            float d4  = max3f(h4dm2, h4dm1, h4d);               // dilate(E_{k+4}), r-5
            float mk3 = 1.f - fmaxf(e3d2 - d4, 0.f);            // 1-delta_{k+3}, r-5

            if (outL & ((unsigned)(r - 4 - y0) < (unsigned)STRIP))
                dst[(size_t)(r - 4) * IMG_W + gx] = e4;         // E_{k+4}

            const int ro = r - 5;
            if (outL & ((unsigned)(ro - y0) < (unsigned)STRIP)) {
                float m = mk0d3 * mk1d2 * mk2d1 * mk3;
                acc[(size_t)ro * IMG_W + gx] = FIRST ? m : av * m;
            }

            h1m2=h1m1;  h1m1=h1;  h1dm2=h1dm1; h1dm1=h1d;
            h2m2=h2m1;  h2m1=h2;  h2dm2=h2dm1; h2dm1=h2d;
            h3m2=h3m1;  h3m1=h3;  h3dm2=h3dm1; h3dm1=h3d;
            h4m2=h4m1;  h4m1=h4;  h4dm2=h4dm1; h4dm1=h4d;
            ad2=ad1;   ad1=a;
            e1d2=e1d1; e1d1=e1;  e2d2=e2d1; e2d1=e2;  e3d2=e3d1; e3d1=e3;
            mk0d3=mk0d2; mk0d2=mk0d1; mk0d1=mk0;
            mk1d2=mk1d1; mk1d1=mk1;  mk2d1=mk2;
        }
    }
}

// ---------------------------------------------------------------------------
// Final kernel: steps 8,9,10 fused with reduction. Reads E8 + acc + other.
// Output row = r-4; output lanes 4..27.
// ---------------------------------------------------------------------------
__global__ __launch_bounds__(128) void final_kernel(
    const float* __restrict__ pred,
    const float* __restrict__ target,
    int srcbuf)
{
    const int z     = blockIdx.z;
    const int skel  = z >> 4;
    const int plane = z & 15;
    const int wtile = blockIdx.x * 4 + (threadIdx.x >> 5);
    const int lane  = threadIdx.x & 31;
    const int y0    = blockIdx.y * STRIP;
    const int yEnd  = y0 + STRIP;

    float s_num = 0.f, s_den = 0.f;

    if (wtile < TILESF) {
        const int  gx   = wtile * COLSF - 4 + lane;
        const bool inX  = (unsigned)gx < (unsigned)IMG_W;
        const bool outL = (lane >= 4) & (lane <= 27) & inX;

        const size_t pbase = (size_t)plane * PLANE_SZ;
        const float* __restrict__ src   = &g_E[skel][srcbuf][pbase];
        const float* __restrict__ acc   = &g_acc[skel][pbase];
        // skel_p pairs with raw target; skel_t pairs with sigmoid(pred)
        const float* __restrict__ other = (skel ? pred : target) + pbase;

        auto ldrow = [&](int rr) -> float {
            float v = 1e30f;
            if (((unsigned)rr < (unsigned)IMG_H) & inX)
                v = __ldg(&src[(size_t)rr * IMG_W + gx]);
            return v;
        };

        float abuf[4];
        float accbuf[4] = {0.f, 0.f, 0.f, 0.f};
        float obuf[4]   = {0.f, 0.f, 0.f, 0.f};
        #pragma unroll
        for (int j = 0; j < 4; j++) abuf[j] = ldrow(y0 - 4 + j);

        float h1m1=0,h1m2=0,h1dm1=0,h1dm2=0;
        float h2m1=0,h2m2=0,h2dm1=0,h2dm2=0;
        float h3m1=0,h3m2=0,h3dm1=0,h3dm2=0;
        float ad1=0,ad2=0,e1d1=0,e1d2=0,e2d1=0,e2d2=0;
        float mk0d1=0,mk0d2=0,mk1d1=0;

        // rows y0-4 .. yEnd+3 (STRIP+8 iters); slot j == (r-(y0-4)) mod 4
        for (int rb = y0 - 4; rb <= yEnd; rb += 4) {
            #pragma unroll
            for (int j = 0; j < 4; j++) {
                const int r = rb + j;
                float a = abuf[j];
                abuf[j] = ldrow(r + 4);
                float av = accbuf[j];                    // acc row r-4
                float ov = obuf[j];
                if ((r >= y0) & (r < yEnd) & outL) {
                    size_t g = (size_t)r * IMG_W + gx;
                    accbuf[j] = acc[g];
                    obuf[j]   = __ldg(&other[g]);
                }

                float h1 = hmin3(a);
                float e1 = min3f(h1m2, h1m1, h1);                   // E9, r-1
                bool  m1 = ((unsigned)(r - 1) < (unsigned)IMG_H) & inX;
                float h1d = hmax3(m1 ? e1 : -1e30f);
                float h2  = hmin3(m1 ? e1 :  1e30f);
                float e2 = min3f(h2m2, h2m1, h2);                   // E10, r-2
                bool  m2 = ((unsigned)(r - 2) < (unsigned)IMG_H) & inX;
                float h2d = hmax3(m2 ? e2 : -1e30f);
                float h3  = hmin3(m2 ? e2 :  1e30f);
                float e3 = min3f(h3m2, h3m1, h3);                   // E11, r-3
                bool  m3 = ((unsigned)(r - 3) < (unsigned)IMG_H) & inX;
                float h3d = hmax3(m3 ? e3 : -1e30f);

                float d1  = max3f(h1dm2, h1dm1, h1d);               // dilate(E9), r-2
                float mk0 = 1.f - fmaxf(ad2 - d1, 0.f);             // 1-delta8, r-2
                float d2  = max3f(h2dm2, h2dm1, h2d);               // dilate(E10), r-3
                float mk1 = 1.f - fmaxf(e1d2 - d2, 0.f);            // 1-delta9, r-3
                float d3  = max3f(h3dm2, h3dm1, h3d);               // dilate(E11), r-4
                float dl  = fmaxf(e2d2 - d3, 0.f);                  // delta10, r-4

                const int ro = r - 4;
                if (outL & ((unsigned)(ro - y0) < (unsigned)STRIP)) {
                    float sp = 1.f - av * (mk0d2 * mk1d1 * (1.f - dl));
                    s_num += sp * (skel ? sigmoidf(ov) : ov);
                    s_den += sp;
                }

                h1m2=h1m1;  h1m1=h1;  h1dm2=h1dm1; h1dm1=h1d;
                h2m2=h2m1;  h2m1=h2;  h2dm2=h2dm1; h2dm1=h2d;
                h3m2=h3m1;  h3m1=h3;  h3dm2=h3dm1; h3dm1=h3d;
                ad2=ad1;   ad1=a;
                e1d2=e1d1; e1d1=e1;  e2d2=e2d1; e2d1=e2;
                mk0d2=mk0d1; mk0d1=mk0;  mk1d1=mk1;
            }
        }
    }

    #pragma unroll
    for (int off = 16; off; off >>= 1) {
        s_num += __shfl_down_sync(0xffffffffu, s_num, off);
        s_den += __shfl_down_sync(0xffffffffu, s_den, off);
    }
    __shared__ float red[4][2];
    int warp = threadIdx.x >> 5;
    if ((threadIdx.x & 31) == 0) { red[warp][0] = s_num; red[warp][1] = s_den; }
    __syncthreads();
    if (threadIdx.x < 2) {
        float s = red[0][threadIdx.x] + red[1][threadIdx.x]
                + red[2][threadIdx.x] + red[3][threadIdx.x];
        atomicAdd(&g_sums[plane * 4 + skel * 2 + threadIdx.x], s);
    }
}

__global__ void finalize_kernel(float* __restrict__ out) {
    if (threadIdx.x == 0 && blockIdx.x == 0) {
        const float eps = 1e-6f;
        float total = 0.f;
        #pragma unroll
        for (int pl = 0; pl < NPLANES; pl++) {
            float spt = g_sums[pl * 4 + 0];
            float sp  = g_sums[pl * 4 + 1];
            float stp = g_sums[pl * 4 + 2];
            float st  = g_sums[pl * 4 + 3];
            float tprec = spt / (sp + eps);
            float tsens = stp / (st + eps);
            total += 1.0f - 2.0f * tprec * tsens / (tprec + tsens + eps);
        }
        out[0] = total * (1.0f / (float)NPLANES);
    }
}

extern "C" void kernel_launch(void* const* d_in, const int* in_sizes, int n_in,
                              void* d_out, int out_size)
{
    (void)in_sizes; (void)n_in; (void)out_size;
    const float* pred   = (const float*)d_in[0];
    const float* target = (const float*)d_in[1];
    float* out = (float*)d_out;

    zero_sums_kernel<<<1, 64>>>();

    dim3 qgrid((TILES4 + 3) / 4, IMG_H / STRIP, NPLANES * 2);   // 12 x 8 x 32
    dim3 fgrid((TILESF + 3) / 4, IMG_H / STRIP, NPLANES * 2);   // 11 x 8 x 32
    dim3 blk(128);

    // steps 0-3 -> E4 (buf0); 4-7 -> E8 (buf1); 8-10 + reduce
    quad_kernel<true ><<<qgrid, blk>>>(pred, target, 0, 0);
    quad_kernel<false><<<qgrid, blk>>>(pred, target, 0, 1);
    final_kernel<<<fgrid, blk>>>(pred, target, 1);

    finalize_kernel<<<1, 32>>>(out);
}